// round 9
// baseline (speedup 1.0000x reference)
#include <cuda_runtime.h>

#define FULLMASK 0xffffffffu
#define NTAGS 32
#define BOS_IDX 30
#define EOS_IDX 31
#define L2E 1.4426950408889634f
#define LN2 0.6931471805599453f

typedef unsigned long long ull;

static __device__ __forceinline__ void ffma2(ull& d, ull a, ull b) {
    asm("fma.rn.f32x2 %0, %1, %2, %0;" : "+l"(d) : "l"(a), "l"(b));
}
static __device__ __forceinline__ ull add2(ull a, ull b) {
    ull r;
    asm("add.rn.f32x2 %0, %1, %2;" : "=l"(r) : "l"(a), "l"(b));
    return r;
}
static __device__ __forceinline__ float ex2_(float x) {
    float r; asm("ex2.approx.f32 %0, %1;" : "=f"(r) : "f"(x)); return r;
}
static __device__ __forceinline__ float lg2_(float x) {
    float r; asm("lg2.approx.f32 %0, %1;" : "=f"(r) : "f"(x)); return r;
}
static __device__ __forceinline__ float hsum2(ull a, ull b) {
    ull s = add2(a, b);
    float x, y;
    asm("mov.b64 {%0,%1}, %2;" : "=f"(x), "=f"(y) : "l"(s));
    return x + y;
}

// Half-split warp matvec (R7/R8-verified body): lane l stores x_l, reads its
// 16-element half (4x LDS.128), computes half-dots for rows l and l^16 of the
// given matrix, combines with one shfl_xor(16). No __syncwarp (convergent
// lanes + in-order per-warp LSU; verified R5/R6/R8).
static __device__ __forceinline__ float mv_half(
    unsigned stA, unsigned ldA, float x, const ull* eu, const ull* ew)
{
    asm volatile("st.shared.f32 [%0], %1;" :: "r"(stA), "f"(x) : "memory");
    ull p0, p1, p2, p3;
    asm volatile("ld.shared.v2.u64 {%0,%1}, [%2];"
                 : "=l"(p0), "=l"(p1) : "r"(ldA));
    asm volatile("ld.shared.v2.u64 {%0,%1}, [%2];"
                 : "=l"(p2), "=l"(p3) : "r"(ldA + 16));
    ull U0 = 0ull, U1 = 0ull, W0 = 0ull, W1 = 0ull;
    ffma2(U0, eu[0], p0);  ffma2(U1, eu[1], p1);
    ffma2(W0, ew[0], p0);  ffma2(W1, ew[1], p1);
    ffma2(U0, eu[2], p2);  ffma2(U1, eu[3], p3);
    ffma2(W0, ew[2], p2);  ffma2(W1, ew[3], p3);
    asm volatile("ld.shared.v2.u64 {%0,%1}, [%2];"
                 : "=l"(p0), "=l"(p1) : "r"(ldA + 32));
    asm volatile("ld.shared.v2.u64 {%0,%1}, [%2];"
                 : "=l"(p2), "=l"(p3) : "r"(ldA + 48));
    ffma2(U0, eu[4], p0);  ffma2(U1, eu[5], p1);
    ffma2(W0, ew[4], p0);  ffma2(W1, ew[5], p1);
    ffma2(U0, eu[6], p2);  ffma2(U1, eu[7], p3);
    ffma2(W0, ew[6], p2);  ffma2(W1, ew[7], p3);
    float uu = hsum2(U0, U1);
    float ww = hsum2(W0, W1);
    return uu + __shfl_xor_sync(FULLMASK, ww, 16);
}

// Forward/backward split: warp 0 runs forward matvecs for emissions 1..M,
// warp 1 runs backward (G^T) matvecs for emissions T-1..M+1, both with the
// lag-1 log2 rescaling (fwd anchored at s_EOS, bwd at s_0; G's EOS column is
// zero so v_EOS dies and cannot anchor).  Join: Z = sum_i v_M,i * beta_M,i,
// logZ = (lg2(Z) + Cf + Cb) * ln2.   Serial depth halves: 511 -> 256.
__global__ __launch_bounds__(64, 1) void crf_fb_kernel(
    const float* __restrict__ emission,   // [B, T, 32]
    const float* __restrict__ trans,      // [32, 32]
    float* __restrict__ out,              // [B]
    int B, int T)
{
    const int lane = threadIdx.x & 31;
    const int w    = threadIdx.x >> 5;    // 0 = forward, 1 = backward
    const int b    = blockIdx.x;

    __shared__ __align__(16) float sx[2][2][NTAGS];  // exchange [warp][buf][tag]
    __shared__ float sfin[2][NTAGS];                 // join vectors
    __shared__ float scst[2];                        // join constants

    // matrix half-rows for this lane: forward uses G rows (lane, lane^16),
    // backward uses G^T rows, i.e. G columns (lane, lane^16). Both over the
    // lane's beta-half columns h..h+15, packed f32x2.
    const int h  = lane & 16;
    const int pr = lane ^ 16;
    ull eu[8], ew[8];
    #pragma unroll
    for (int q = 0; q < 8; q++) {
        float x, y, z, u;
        if (w == 0) {
            x = expf(trans[lane * NTAGS + h + 2 * q]);
            y = expf(trans[lane * NTAGS + h + 2 * q + 1]);
            z = expf(trans[pr   * NTAGS + h + 2 * q]);
            u = expf(trans[pr   * NTAGS + h + 2 * q + 1]);
        } else {
            x = expf(trans[(h + 2 * q)     * NTAGS + lane]);
            y = expf(trans[(h + 2 * q + 1) * NTAGS + lane]);
            z = expf(trans[(h + 2 * q)     * NTAGS + pr]);
            u = expf(trans[(h + 2 * q + 1) * NTAGS + pr]);
        }
        asm("mov.b64 %0, {%1,%2};" : "=l"(eu[q]) : "f"(x), "f"(y));
        asm("mov.b64 %0, {%1,%2};" : "=l"(ew[q]) : "f"(z), "f"(u));
    }

    const float* emb = emission + (size_t)b * T * NTAGS + lane;
    const int M = (T - 1) >> 1;            // forward handles 1..M, bwd the rest

    const unsigned sa  = (unsigned)__cvta_generic_to_shared(&sx[w][0][0]);
    const unsigned BUF = NTAGS * 4;
    unsigned stA = sa + (unsigned)lane * 4;
    unsigned ldA = sa + (unsigned)h * 4;

    float beta, Cs, sE;
    if (w == 0) {
        // forward init: step 0 analytic (only BOS survives), EOS-anchored
        float a2 = (emb[0] + trans[lane * NTAGS + BOS_IDX]) * L2E;
        Cs = __shfl_sync(FULLMASK, a2, EOS_IDX);
        beta = ex2_(a2 - Cs);              // 0 on dead BOS lane
        sE = 1.0f;

        float ring[4];
        #pragma unroll
        for (int i = 0; i < 4; i++) {
            int tt = (i + 1 < T) ? (i + 1) : (T - 1);
            ring[i] = emb[(size_t)tt * NTAGS];
        }

        #pragma unroll 4
        for (int it = 1; it <= M; ++it) {
            float emv = ring[0];
            ring[0] = ring[1]; ring[1] = ring[2]; ring[2] = ring[3];
            int tp = (it + 4 < T) ? (it + 4) : (T - 1);
            ring[3] = emb[(size_t)tp * NTAGS];

            float D = lg2_(sE);            // lag-1, off-chain
            Cs += D;
            float K = ex2_(fmaf(emv, L2E, -D));

            stA ^= BUF; ldA ^= BUF;
            float s = mv_half(stA, ldA, beta, eu, ew);
            sE = __shfl_sync(FULLMASK, s, EOS_IDX);
            beta = s * K;                  // post-multiply (forward)
        }
    } else {
        // backward init: v = w = exp(trans[EOS,:]); w_EOS = exp(-1000) = 0
        beta = expf(trans[EOS_IDX * NTAGS + lane]);
        Cs = 0.0f;
        sE = 1.0f;
        int nb = T - 1 - M;                // emissions T-1 .. M+1

        float ring[4];
        #pragma unroll
        for (int i = 0; i < 4; i++) {
            int tt = T - 1 - i; if (tt < 0) tt = 0;
            ring[i] = emb[(size_t)tt * NTAGS];
        }

        #pragma unroll 4
        for (int it = 0; it < nb; ++it) {
            float emv = ring[0];
            ring[0] = ring[1]; ring[1] = ring[2]; ring[2] = ring[3];
            int tn = T - 1 - it - 4; if (tn < 0) tn = 0;
            ring[3] = emb[(size_t)tn * NTAGS];

            float D = lg2_(sE);            // lag-1, off-chain
            Cs += D;
            float K = ex2_(fmaf(emv, L2E, -D));

            float u = beta * K;            // pre-multiply (backward)
            stA ^= BUF; ldA ^= BUF;
            float s = mv_half(stA, ldA, u, eu, ew);
            sE = __shfl_sync(FULLMASK, s, 0);   // anchor lane 0
            beta = s;
        }
    }

    // join
    sfin[w][lane] = beta;
    if (lane == 0) scst[w] = Cs;
    __syncthreads();

    if (w == 0) {
        float p = sfin[0][lane] * sfin[1][lane];
        #pragma unroll
        for (int o = 16; o; o >>= 1)
            p += __shfl_xor_sync(FULLMASK, p, o);
        if (lane == 0)
            out[b] = (lg2_(p) + scst[0] + scst[1]) * LN2;
    }
}

extern "C" void kernel_launch(void* const* d_in, const int* in_sizes, int n_in,
                              void* d_out, int out_size)
{
    const float* em = (const float*)d_in[0];
    const float* tr = (const float*)d_in[1];
    long long em_elems = in_sizes[0];
    if (n_in >= 2 && in_sizes[0] == NTAGS * NTAGS && in_sizes[1] > NTAGS * NTAGS) {
        em = (const float*)d_in[1];
        tr = (const float*)d_in[0];
        em_elems = in_sizes[1];
    }

    int B = out_size;
    int T = (int)(em_elems / ((long long)B * NTAGS));

    // one CTA (64 threads = fwd warp + bwd warp) per sequence
    crf_fb_kernel<<<B, 64>>>(em, tr, (float*)d_out, B, T);
}